// round 2
// baseline (speedup 1.0000x reference)
#include <cuda_runtime.h>
#include <math_constants.h>
#include <cstdint>

#define DD 128
#define BQ 32
#define KTOP 16
#define TILE_R 128
#define THREADS 128
#define NCTA 296
#define ASTRIDE 129

// shared layout (floats) for k_main
#define OFF_A   0
#define OFF_Q   (OFF_A + TILE_R*ASTRIDE)      // 16512  (byte off 66048, 16B aligned)
#define OFF_SC  (OFF_Q + DD*BQ)               // +4096
#define OFF_MN  (OFF_SC + BQ*TILE_R)          // +4096
#define OFF_QN  (OFF_MN + TILE_R)             // +128
#define SMEM_FLOATS (OFF_QN + BQ)
#define SMEM_BYTES (SMEM_FLOATS * 4)

__device__ float g_q[BQ*DD];
__device__ float g_qn[BQ];
__device__ float g_cand_s[NCTA*BQ*KTOP];
__device__ int   g_cand_i[NCTA*BQ*KTOP];
__device__ float g_minred[NCTA*BQ];

// ---------------------------------------------------------------------------
// Kernel 1: q = query @ Wq^T + bq ; ||q||
// ---------------------------------------------------------------------------
__global__ void k_setup(const float* __restrict__ query,
                        const float* __restrict__ Wq,
                        const float* __restrict__ bqv) {
    __shared__ float sq[DD];
    __shared__ float red[DD];
    int b = blockIdx.x;
    int j = threadIdx.x;
    sq[j] = query[b*DD + j];
    __syncthreads();
    float acc = 0.f;
    #pragma unroll 8
    for (int d = 0; d < DD; d++) acc = fmaf(sq[d], Wq[j*DD + d], acc);
    float v = acc + bqv[j];
    g_q[b*DD + j] = v;
    red[j] = v * v;
    __syncthreads();
    for (int s = 64; s > 0; s >>= 1) {
        if (j < s) red[j] += red[j + s];
        __syncthreads();
    }
    if (j == 0) g_qn[b] = sqrtf(red[0]);
}

// ---------------------------------------------------------------------------
// Kernel 2: tiled dot + score + per-CTA exact top-16 + min-d2
// ---------------------------------------------------------------------------
__global__ void __launch_bounds__(THREADS, 2)
k_main(const float* __restrict__ mem, const float* __restrict__ imp,
       const int* __restrict__ ts, const int* __restrict__ ctp,
       int N, int tpc) {
    extern __shared__ float smf[];
    float* sA  = smf + OFF_A;
    float* sQ  = smf + OFF_Q;
    float* sSC = smf + OFF_SC;
    float* sMN = smf + OFF_MN;
    float* sQN = smf + OFF_QN;

    const int t   = threadIdx.x;
    const int cta = blockIdx.x;
    const int qg  = t & 3;          // query group: 8 queries
    const int rg  = t >> 2;         // row group: 4 rows
    const int b0  = qg * 8;
    const int r0  = rg * 4;

    // stage q transposed: sQ[k*32 + b]
    for (int o = t; o < BQ*DD; o += THREADS) {
        int b = o >> 7, k = o & 127;
        sQ[k*BQ + b] = g_q[o];
    }
    if (t < BQ) sQN[t] = g_qn[t];

    const float ctf1 = (float)(*ctp) + 1.0f;

    // per-thread min of (||m||^2 - 2 q.m) for 8 queries
    float lmin[8];
    #pragma unroll
    for (int j = 0; j < 8; j++) lmin[j] = CUDART_INF_F;

    // top-16 state (scanner threads t<32 only; local-mem arrays, rare updates)
    float hs[KTOP]; int hi[KTOP];
    #pragma unroll
    for (int j = 0; j < KTOP; j++) { hs[j] = -CUDART_INF_F; hi[j] = 0x7fffffff; }
    float thr = -CUDART_INF_F;

    __syncthreads();

    const long tile0 = (long)cta * tpc;
    for (int it = 0; it < tpc; it++) {
        int base = (int)((tile0 + it) * TILE_R);
        if (base >= N) break;

        // ---- load tile (coalesced gmem, conflict-free smem stores) ----
        {
            const float4* gsrc = (const float4*)mem + (size_t)base * (DD/4);
            #pragma unroll
            for (int j = 0; j < (TILE_R*DD/4)/THREADS; j++) {
                int fi  = t + THREADS*j;   // 0..4095
                int row = fi >> 5;
                int c4  = fi & 31;
                float4 v = make_float4(0.f, 0.f, 0.f, 0.f);
                if (base + row < N) v = gsrc[fi];
                int off = row*ASTRIDE + c4*4;
                sA[off+0] = v.x; sA[off+1] = v.y; sA[off+2] = v.z; sA[off+3] = v.w;
            }
        }
        __syncthreads();

        // ---- row norms^2 (conflict-free: bank = (t+k) mod 32) ----
        {
            float s = 0.f;
            const float* ra = sA + t*ASTRIDE;
            #pragma unroll 8
            for (int k = 0; k < DD; k++) { float v = ra[k]; s = fmaf(v, v, s); }
            sMN[t] = s;
        }

        // ---- dots: 4 rows x 8 queries per thread ----
        float acc[4][8];
        #pragma unroll
        for (int r = 0; r < 4; r++)
            #pragma unroll
            for (int b = 0; b < 8; b++) acc[r][b] = 0.f;

        const float* A0 = sA + (r0+0)*ASTRIDE;
        const float* A1 = sA + (r0+1)*ASTRIDE;
        const float* A2 = sA + (r0+2)*ASTRIDE;
        const float* A3 = sA + (r0+3)*ASTRIDE;
        const float* Qb = sQ + b0;
        #pragma unroll 4
        for (int k = 0; k < DD; k++) {
            float a0 = A0[k], a1 = A1[k], a2 = A2[k], a3 = A3[k];
            float4 qx = *(const float4*)(Qb + k*BQ);
            float4 qy = *(const float4*)(Qb + k*BQ + 4);
            float qv[8] = {qx.x, qx.y, qx.z, qx.w, qy.x, qy.y, qy.z, qy.w};
            #pragma unroll
            for (int b = 0; b < 8; b++) {
                acc[0][b] = fmaf(a0, qv[b], acc[0][b]);
                acc[1][b] = fmaf(a1, qv[b], acc[1][b]);
                acc[2][b] = fmaf(a2, qv[b], acc[2][b]);
                acc[3][b] = fmaf(a3, qv[b], acc[3][b]);
            }
        }

        // ---- epilogue: exact reference score, dump to sSC, track min-d2 ----
        #pragma unroll
        for (int r = 0; r < 4; r++) {
            int rl  = r0 + r;
            int row = base + rl;
            bool valid = (row < N);
            float mn2 = 0.f, mn = 0.f, rec = 0.f, w = 0.f;
            if (valid) {
                mn2 = sMN[rl];
                mn  = sqrtf(mn2);
                rec = ((float)ts[row] + 1.0f) / ctf1;
                w   = 0.5f + 0.5f * imp[row];
            }
            #pragma unroll
            for (int b = 0; b < 8; b++) {
                float sc = -CUDART_INF_F;
                if (valid) {
                    float dot = acc[r][b];
                    float den = fmaxf(sQN[b0+b] * mn, 1e-8f);
                    sc = (0.7f * (dot/den) + 0.3f * rec) * w;
                    lmin[b] = fminf(lmin[b], fmaf(-2.0f, dot, mn2));
                }
                sSC[(b0+b)*TILE_R + rl] = sc;
            }
        }
        __syncthreads();

        // ---- scanner threads: exact top-16 insertion for query t ----
        if (t < BQ) {
            const float* myrow = sSC + t*TILE_R;
            for (int e = 0; e < TILE_R; e++) {
                float sc = myrow[e];
                if (sc > thr) {
                    int idx = base + e;
                    int p = KTOP - 1;
                    #pragma unroll
                    for (int s = KTOP - 1; s > 0; s--) {
                        if (sc > hs[s-1]) { hs[s] = hs[s-1]; hi[s] = hi[s-1]; p = s-1; }
                    }
                    hs[p] = sc; hi[p] = idx;
                    thr = hs[KTOP-1];
                }
            }
        }
        __syncthreads();
    }

    // ---- reduce lmin across threads (reuse sSC as [query][rg]) ----
    #pragma unroll
    for (int j = 0; j < 8; j++) sSC[(b0+j)*BQ + rg] = lmin[j];
    __syncthreads();
    if (t < BQ) {
        float m = CUDART_INF_F;
        #pragma unroll 4
        for (int i = 0; i < BQ; i++) m = fminf(m, sSC[t*BQ + i]);
        g_minred[cta*BQ + t] = m;
        // write candidates
        float* cs = g_cand_s + ((size_t)cta*BQ + t) * KTOP;
        int*   ci = g_cand_i + ((size_t)cta*BQ + t) * KTOP;
        #pragma unroll
        for (int j = 0; j < KTOP; j++) { cs[j] = hs[j]; ci[j] = hi[j]; }
    }
}

// ---------------------------------------------------------------------------
// Kernel 3: merge per-CTA candidates -> exact global top-16 + novelty
// ---------------------------------------------------------------------------
#define MCAND (NCTA*KTOP)
__global__ void __launch_bounds__(256)
k_merge(float* __restrict__ out) {
    __shared__ float cs[MCAND];
    __shared__ int   ci[MCAND];
    __shared__ float rv[256];
    __shared__ int   ri[256];
    __shared__ int   rp[256];

    int q = blockIdx.x;
    int t = threadIdx.x;

    for (int i = t; i < MCAND; i += 256) {
        int c = i >> 4, j = i & (KTOP-1);
        size_t g = ((size_t)c*BQ + q) * KTOP + j;
        cs[i] = g_cand_s[g];
        ci[i] = g_cand_i[g];
    }
    __syncthreads();

    for (int pass = 0; pass < KTOP; pass++) {
        float bv = -CUDART_INF_F; int bi = 0x7fffffff; int bp = 0;
        for (int i = t; i < MCAND; i += 256) {
            float v = cs[i]; int id = ci[i];
            if (v > bv || (v == bv && id < bi)) { bv = v; bi = id; bp = i; }
        }
        rv[t] = bv; ri[t] = bi; rp[t] = bp;
        __syncthreads();
        for (int s = 128; s > 0; s >>= 1) {
            if (t < s) {
                if (rv[t+s] > rv[t] || (rv[t+s] == rv[t] && ri[t+s] < ri[t])) {
                    rv[t] = rv[t+s]; ri[t] = ri[t+s]; rp[t] = rp[t+s];
                }
            }
            __syncthreads();
        }
        if (t == 0) {
            out[q*KTOP + pass]             = rv[0];
            out[BQ*KTOP + q*KTOP + pass]   = (float)ri[0];
            cs[rp[0]] = -CUDART_INF_F;
        }
        __syncthreads();
    }

    // novelty
    float m = CUDART_INF_F;
    for (int c = t; c < NCTA; c += 256) m = fminf(m, g_minred[c*BQ + q]);
    rv[t] = m;
    __syncthreads();
    for (int s = 128; s > 0; s >>= 1) {
        if (t < s) rv[t] = fminf(rv[t], rv[t+s]);
        __syncthreads();
    }
    if (t == 0) {
        float qn = g_qn[q];
        float d2 = qn*qn + rv[0];
        float dist = sqrtf(fmaxf(d2, 0.0f));
        out[2*BQ*KTOP + q] = fminf(1.0f, dist * 0.1f);
    }
}

// ---------------------------------------------------------------------------
extern "C" void kernel_launch(void* const* d_in, const int* in_sizes, int n_in,
                              void* d_out, int out_size) {
    const float* query = (const float*)d_in[0];
    const float* mem   = (const float*)d_in[1];
    const float* imp   = (const float*)d_in[2];
    const int*   ts    = (const int*)d_in[3];
    const float* Wq    = (const float*)d_in[4];
    const float* bqv   = (const float*)d_in[5];
    const int*   ct    = (const int*)d_in[6];

    int N = in_sizes[1] / DD;
    float* out = (float*)d_out;

    cudaFuncSetAttribute(k_main, cudaFuncAttributeMaxDynamicSharedMemorySize, SMEM_BYTES);

    k_setup<<<BQ, DD>>>(query, Wq, bqv);
    int tpc = (N + NCTA*TILE_R - 1) / (NCTA*TILE_R);
    k_main<<<NCTA, THREADS, SMEM_BYTES>>>(mem, imp, ts, ct, N, tpc);
    k_merge<<<BQ, 256>>>(out);
}

// round 3
// speedup vs baseline: 1.3968x; 1.3968x over previous
#include <cuda_runtime.h>
#include <math_constants.h>
#include <cstdint>

#define DD 128
#define BQ 32
#define KTOP 16
#define TILE_R 128
#define THREADS 128
#define NCTA 296
#define SST 129   // sSC row stride (odd -> conflict-free)

// shared layout (floats) for k_main
#define OFF_A   0
#define OFF_Q   (OFF_A + TILE_R*DD)        // 16384
#define OFF_SC  (OFF_Q + DD*BQ)            // +4096
#define OFF_MN  (OFF_SC + BQ*SST)          // +4128
#define OFF_CB  (OFF_MN + TILE_R)          // +128
#define SMEM_FLOATS (OFF_CB + BQ)
#define SMEM_BYTES  (SMEM_FLOATS*4)

__device__ float g_q[BQ*DD];
__device__ float g_qn[BQ];
__device__ float g_cb[BQ];
__device__ float g_cand_s[NCTA*BQ*KTOP];
__device__ int   g_cand_i[NCTA*BQ*KTOP];
__device__ float g_minred[NCTA*BQ];

// ---- packed f32x2 helpers (sm_103a) ----
__device__ __forceinline__ unsigned long long dup2(float a) {
    unsigned long long d;
    asm("mov.b64 %0, {%1, %1};" : "=l"(d) : "f"(a));
    return d;
}
__device__ __forceinline__ void fma2(unsigned long long& d,
                                     unsigned long long a,
                                     unsigned long long b) {
    asm("fma.rn.f32x2 %0, %1, %2, %0;" : "+l"(d) : "l"(a), "l"(b));
}
__device__ __forceinline__ void unpack2(unsigned long long v, float& lo, float& hi) {
    asm("mov.b64 {%0, %1}, %2;" : "=f"(lo), "=f"(hi) : "l"(v));
}
__device__ __forceinline__ float rsqrt_nr(float x) {
    float r;
    asm("rsqrt.approx.f32 %0, %1;" : "=f"(r) : "f"(x));
    float h = 0.5f * x;
    r = r * fmaf(-h * r, r, 1.5f);   // one Newton step -> ~full fp32 precision
    return r;
}

// swizzled A addressing: element (row, k), chunk c = k>>2
__device__ __forceinline__ int a_off(int row, int c) {
    return row * DD + (((c) ^ (row & 31)) << 2);
}

// ---------------------------------------------------------------------------
// Kernel 1: q = query @ Wq^T + bq ; ||q|| ; 0.7/||q||
// ---------------------------------------------------------------------------
__global__ void k_setup(const float* __restrict__ query,
                        const float* __restrict__ Wq,
                        const float* __restrict__ bqv) {
    __shared__ float sq[DD];
    __shared__ float red[DD];
    int b = blockIdx.x;
    int j = threadIdx.x;
    sq[j] = query[b*DD + j];
    __syncthreads();
    const float* wr = Wq + (size_t)j * DD;
    float a0 = 0.f, a1 = 0.f, a2 = 0.f, a3 = 0.f;
    #pragma unroll 8
    for (int d = 0; d < DD; d += 4) {
        a0 = fmaf(sq[d+0], wr[d+0], a0);
        a1 = fmaf(sq[d+1], wr[d+1], a1);
        a2 = fmaf(sq[d+2], wr[d+2], a2);
        a3 = fmaf(sq[d+3], wr[d+3], a3);
    }
    float v = ((a0 + a1) + (a2 + a3)) + bqv[j];
    g_q[b*DD + j] = v;
    red[j] = v * v;
    __syncthreads();
    for (int s = 64; s > 0; s >>= 1) {
        if (j < s) red[j] += red[j + s];
        __syncthreads();
    }
    if (j == 0) {
        float qn = sqrtf(red[0]);
        g_qn[b] = qn;
        g_cb[b] = 0.7f / qn;
    }
}

// ---------------------------------------------------------------------------
// Kernel 2: tiled dots (FFMA2) + score + per-CTA exact top-16 + min-d2
// ---------------------------------------------------------------------------
__global__ void __launch_bounds__(THREADS, 2)
k_main(const float* __restrict__ mem, const float* __restrict__ imp,
       const int* __restrict__ ts, const int* __restrict__ ctp,
       int N, int tpc) {
    extern __shared__ float smf[];
    float* sA  = smf + OFF_A;
    float* sQ  = smf + OFF_Q;
    float* sSC = smf + OFF_SC;
    float* sMN = smf + OFF_MN;
    float* sCB = smf + OFF_CB;

    const int t   = threadIdx.x;
    const int cta = blockIdx.x;
    const int qg  = t & 3;          // 8 queries (4 f32x2 pairs)
    const int rg  = t >> 2;         // 4 rows
    const int b0  = qg * 8;
    const int r0  = rg * 4;
    const int trs = t & 31;

    // stage q transposed: sQ[k*32 + b]  (one-time; conflicts irrelevant)
    for (int o = t; o < BQ*DD; o += THREADS) {
        int b = o >> 7, k = o & 127;
        sQ[k*BQ + b] = g_q[o];
    }
    if (t < BQ) sCB[t] = g_cb[t];

    const float inv_ct1 = 1.0f / ((float)(*ctp) + 1.0f);

    float lmn[8];
    #pragma unroll
    for (int j = 0; j < 8; j++) lmn[j] = CUDART_INF_F;

    float hs[KTOP]; int hi[KTOP];
    #pragma unroll
    for (int j = 0; j < KTOP; j++) { hs[j] = -CUDART_INF_F; hi[j] = 0x7fffffff; }
    float thr = -CUDART_INF_F;

    __syncthreads();

    const int rsw0 = (r0+0) & 31, rsw1 = (r0+1) & 31, rsw2 = (r0+2) & 31, rsw3 = (r0+3) & 31;
    const float* A0 = sA + (r0+0)*DD;
    const float* A1 = sA + (r0+1)*DD;
    const float* A2 = sA + (r0+2)*DD;
    const float* A3 = sA + (r0+3)*DD;

    const long tile0 = (long)cta * tpc;
    for (int it = 0; it < tpc; it++) {
        int base = (int)((tile0 + it) * TILE_R);
        if (base >= N) break;
        const bool full = (base + TILE_R <= N);

        // ---- load tile: coalesced LDG.128, XOR-swizzled conflict-free STS.128 ----
        {
            const float4* gsrc = (const float4*)mem + (size_t)base * (DD/4);
            #pragma unroll 4
            for (int j = 0; j < (TILE_R*DD/4)/THREADS; j++) {
                int fi  = t + THREADS*j;
                int row = fi >> 5;
                int c   = fi & 31;
                float4 v = make_float4(0.f, 0.f, 0.f, 0.f);
                if (full || base + row < N) v = gsrc[fi];
                *(float4*)(sA + row*DD + ((c ^ (row & 31)) << 2)) = v;
            }
        }
        __syncthreads();

        // ---- row norms^2 via conflict-free swizzled LDS.128 ----
        {
            float s0 = 0.f, s1 = 0.f;
            const float* ra = sA + t*DD;
            #pragma unroll 8
            for (int c = 0; c < 32; c++) {
                float4 v = *(const float4*)(ra + ((c ^ trs) << 2));
                s0 = fmaf(v.x, v.x, s0); s1 = fmaf(v.y, v.y, s1);
                s0 = fmaf(v.z, v.z, s0); s1 = fmaf(v.w, v.w, s1);
            }
            sMN[t] = s0 + s1;
        }

        // ---- dots: 4 rows x 8 queries per thread, packed f32x2 ----
        unsigned long long acc[4][4];
        #pragma unroll
        for (int r = 0; r < 4; r++)
            #pragma unroll
            for (int p = 0; p < 4; p++) acc[r][p] = 0ULL;

        #pragma unroll 1
        for (int c = 0; c < 32; c++) {
            float4 a0 = *(const float4*)(A0 + ((c ^ rsw0) << 2));
            float4 a1 = *(const float4*)(A1 + ((c ^ rsw1) << 2));
            float4 a2 = *(const float4*)(A2 + ((c ^ rsw2) << 2));
            float4 a3 = *(const float4*)(A3 + ((c ^ rsw3) << 2));
            const float* qbase = sQ + (c*4)*BQ + b0;
            #pragma unroll
            for (int kk = 0; kk < 4; kk++) {
                ulonglong2 qA = *(const ulonglong2*)(qbase + kk*BQ);
                ulonglong2 qB = *(const ulonglong2*)(qbase + kk*BQ + 4);
                float a0k = (kk==0) ? a0.x : (kk==1) ? a0.y : (kk==2) ? a0.z : a0.w;
                float a1k = (kk==0) ? a1.x : (kk==1) ? a1.y : (kk==2) ? a1.z : a1.w;
                float a2k = (kk==0) ? a2.x : (kk==1) ? a2.y : (kk==2) ? a2.z : a2.w;
                float a3k = (kk==0) ? a3.x : (kk==1) ? a3.y : (kk==2) ? a3.z : a3.w;
                unsigned long long d0 = dup2(a0k);
                unsigned long long d1 = dup2(a1k);
                unsigned long long d2 = dup2(a2k);
                unsigned long long d3 = dup2(a3k);
                fma2(acc[0][0], d0, qA.x); fma2(acc[0][1], d0, qA.y);
                fma2(acc[0][2], d0, qB.x); fma2(acc[0][3], d0, qB.y);
                fma2(acc[1][0], d1, qA.x); fma2(acc[1][1], d1, qA.y);
                fma2(acc[1][2], d1, qB.x); fma2(acc[1][3], d1, qB.y);
                fma2(acc[2][0], d2, qA.x); fma2(acc[2][1], d2, qA.y);
                fma2(acc[2][2], d2, qB.x); fma2(acc[2][3], d2, qB.y);
                fma2(acc[3][0], d3, qA.x); fma2(acc[3][1], d3, qA.y);
                fma2(acc[3][2], d3, qB.x); fma2(acc[3][3], d3, qB.y);
            }
        }

        // ---- epilogue: exact score, dump to sSC (stride 129), min-d2 ----
        #pragma unroll
        for (int r = 0; r < 4; r++) {
            int rl  = r0 + r;
            int row = base + rl;
            bool valid = full || (row < N);
            if (valid) {
                float mn2  = sMN[rl];
                float inv  = rsqrt_nr(mn2);
                float rec3 = 0.3f * ((float)ts[row] + 1.0f) * inv_ct1;
                float w    = fmaf(0.5f, imp[row], 0.5f);
                #pragma unroll
                for (int p = 0; p < 4; p++) {
                    float lo, hifv; unpack2(acc[r][p], lo, hifv);
                    int b = b0 + 2*p;
                    float s0 = fmaf(lo  *inv, sCB[b],   rec3) * w;
                    float s1 = fmaf(hifv*inv, sCB[b+1], rec3) * w;
                    sSC[(b  )*SST + rl] = s0;
                    sSC[(b+1)*SST + rl] = s1;
                    lmn[2*p  ] = fminf(lmn[2*p  ], fmaf(-2.0f, lo,   mn2));
                    lmn[2*p+1] = fminf(lmn[2*p+1], fmaf(-2.0f, hifv, mn2));
                }
            } else {
                #pragma unroll
                for (int b = 0; b < 8; b++) sSC[(b0+b)*SST + rl] = -CUDART_INF_F;
            }
        }
        __syncthreads();

        // ---- scanner: exact top-16 insertion for query t (conflict-free) ----
        if (t < BQ) {
            const float* myrow = sSC + t*SST;
            float th = thr;
            #pragma unroll 4
            for (int e = 0; e < TILE_R; e += 4) {
                float v0 = myrow[e+0], v1 = myrow[e+1];
                float v2 = myrow[e+2], v3 = myrow[e+3];
                float mx = fmaxf(fmaxf(v0, v1), fmaxf(v2, v3));
                if (mx > th) {
                    #pragma unroll
                    for (int u = 0; u < 4; u++) {
                        float sc = (u==0)?v0:(u==1)?v1:(u==2)?v2:v3;
                        if (sc > th) {
                            int idx = base + e + u;
                            int pos = KTOP - 1;
                            #pragma unroll
                            for (int s = KTOP - 1; s > 0; s--) {
                                if (sc > hs[s-1]) { hs[s] = hs[s-1]; hi[s] = hi[s-1]; pos = s-1; }
                            }
                            hs[pos] = sc; hi[pos] = idx;
                            th = hs[KTOP-1];
                        }
                    }
                }
            }
            thr = th;
        }
        __syncthreads();
    }

    // ---- reduce lmn across threads (reuse sSC as [query][rowgroup]) ----
    #pragma unroll
    for (int j = 0; j < 8; j++) sSC[(b0+j)*BQ + rg] = lmn[j];
    __syncthreads();
    if (t < BQ) {
        float m = CUDART_INF_F;
        #pragma unroll 4
        for (int i = 0; i < BQ; i++) m = fminf(m, sSC[t*BQ + i]);
        g_minred[cta*BQ + t] = m;
        float* cs = g_cand_s + ((size_t)cta*BQ + t) * KTOP;
        int*   ci = g_cand_i + ((size_t)cta*BQ + t) * KTOP;
        #pragma unroll
        for (int j = 0; j < KTOP; j++) { cs[j] = hs[j]; ci[j] = hi[j]; }
    }
}

// ---------------------------------------------------------------------------
// Kernel 3: merge per-CTA candidates -> exact global top-16 + novelty
// ---------------------------------------------------------------------------
#define MCAND (NCTA*KTOP)
__global__ void __launch_bounds__(256)
k_merge(float* __restrict__ out) {
    __shared__ float cs[MCAND];
    __shared__ int   ci[MCAND];
    __shared__ float rv[256];
    __shared__ int   ri[256];
    __shared__ int   rp[256];

    int q = blockIdx.x;
    int t = threadIdx.x;

    for (int i = t; i < MCAND; i += 256) {
        int c = i >> 4, j = i & (KTOP-1);
        size_t g = ((size_t)c*BQ + q) * KTOP + j;
        cs[i] = g_cand_s[g];
        ci[i] = g_cand_i[g];
    }
    __syncthreads();

    for (int pass = 0; pass < KTOP; pass++) {
        float bv = -CUDART_INF_F; int bi = 0x7fffffff; int bp = 0;
        for (int i = t; i < MCAND; i += 256) {
            float v = cs[i]; int id = ci[i];
            if (v > bv || (v == bv && id < bi)) { bv = v; bi = id; bp = i; }
        }
        rv[t] = bv; ri[t] = bi; rp[t] = bp;
        __syncthreads();
        for (int s = 128; s > 0; s >>= 1) {
            if (t < s) {
                if (rv[t+s] > rv[t] || (rv[t+s] == rv[t] && ri[t+s] < ri[t])) {
                    rv[t] = rv[t+s]; ri[t] = ri[t+s]; rp[t] = rp[t+s];
                }
            }
            __syncthreads();
        }
        if (t == 0) {
            out[q*KTOP + pass]           = rv[0];
            out[BQ*KTOP + q*KTOP + pass] = (float)ri[0];
            cs[rp[0]] = -CUDART_INF_F;
        }
        __syncthreads();
    }

    // novelty
    float m = CUDART_INF_F;
    for (int c = t; c < NCTA; c += 256) m = fminf(m, g_minred[c*BQ + q]);
    rv[t] = m;
    __syncthreads();
    for (int s = 128; s > 0; s >>= 1) {
        if (t < s) rv[t] = fminf(rv[t], rv[t+s]);
        __syncthreads();
    }
    if (t == 0) {
        float qn = g_qn[q];
        float d2 = qn*qn + rv[0];
        float dist = sqrtf(fmaxf(d2, 0.0f));
        out[2*BQ*KTOP + q] = fminf(1.0f, dist * 0.1f);
    }
}

// ---------------------------------------------------------------------------
extern "C" void kernel_launch(void* const* d_in, const int* in_sizes, int n_in,
                              void* d_out, int out_size) {
    const float* query = (const float*)d_in[0];
    const float* mem   = (const float*)d_in[1];
    const float* imp   = (const float*)d_in[2];
    const int*   ts    = (const int*)d_in[3];
    const float* Wq    = (const float*)d_in[4];
    const float* bqv   = (const float*)d_in[5];
    const int*   ct    = (const int*)d_in[6];

    int N = in_sizes[1] / DD;
    float* out = (float*)d_out;

    cudaFuncSetAttribute(k_main, cudaFuncAttributeMaxDynamicSharedMemorySize, SMEM_BYTES);

    k_setup<<<BQ, DD>>>(query, Wq, bqv);
    int tpc = (N + NCTA*TILE_R - 1) / (NCTA*TILE_R);
    k_main<<<NCTA, THREADS, SMEM_BYTES>>>(mem, imp, ts, ct, N, tpc);
    k_merge<<<BQ, 256>>>(out);
}